// round 15
// baseline (speedup 1.0000x reference)
#include <cuda_runtime.h>
#include <math.h>
#include <float.h>

// Problem constants
#define B_   2
#define N_   2048
#define D_   2048
#define H_   16
#define HD_  128
#define MR_  (B_ * N_)        // 4096 rows for token-major GEMMs
#define QC_  (3 * D_)         // 6144 qkv columns
#define BHND (B_ * H_ * N_ * HD_)  // 8388608

// Scratch (device globals: allocation-free per harness rules)
__device__ float g_qkv[MR_ * QC_];    // [B*N, 3D]  ~100 MB
__device__ float g_q[BHND];           // RoPE'd Q  [B,H,N,HD]
__device__ float g_k[BHND];           // RoPE'd K  [B,H,N,HD]
__device__ float g_attn[MR_ * D_];    // attn output [B,N,D]

// ---------------------------------------------------------------------------
// SGEMM: C[M,N] = A[M,K] @ B[K,N] + bias[N].  128x128 blocktile, BK=16,
// 256 threads, 8x8 microtile per thread. M%128==0, N%128==0, K%16==0 assumed.
// ---------------------------------------------------------------------------
__global__ __launch_bounds__(256)
void sgemm_bias(const float* __restrict__ A, const float* __restrict__ Bm,
                const float* __restrict__ bias, float* __restrict__ C,
                int M, int N, int K)
{
    __shared__ float As[16][128];   // transposed A tile: As[k][m]
    __shared__ float Bs[16][128];   // Bs[k][n]

    const int tid = threadIdx.x;
    const int bm = blockIdx.y * 128;
    const int bn = blockIdx.x * 128;
    const int tx = tid & 15;        // 16 col-groups
    const int ty = tid >> 4;        // 16 row-groups

    float acc[8][8];
#pragma unroll
    for (int i = 0; i < 8; i++)
#pragma unroll
        for (int j = 0; j < 8; j++) acc[i][j] = 0.f;

    const float* Ab = A + bm * K;

    for (int k0 = 0; k0 < K; k0 += 16) {
        // load A tile (128x16) transposed into As
#pragma unroll
        for (int i = 0; i < 2; i++) {
            int f = tid + i * 256;           // 0..511 float4 slots
            int r = f >> 2;                  // row 0..127
            int kc = (f & 3) << 2;           // k offset 0,4,8,12
            float4 v = *(const float4*)&Ab[r * K + k0 + kc];
            As[kc + 0][r] = v.x;
            As[kc + 1][r] = v.y;
            As[kc + 2][r] = v.z;
            As[kc + 3][r] = v.w;
        }
        // load B tile (16x128)
#pragma unroll
        for (int i = 0; i < 2; i++) {
            int f = tid + i * 256;
            int r = f >> 5;                  // k row 0..15
            int c = (f & 31) << 2;           // col 0..124
            *(float4*)&Bs[r][c] = *(const float4*)&Bm[(k0 + r) * N + bn + c];
        }
        __syncthreads();

#pragma unroll
        for (int kk = 0; kk < 16; kk++) {
            float a[8], b[8];
            *(float4*)&a[0] = *(float4*)&As[kk][ty * 8];
            *(float4*)&a[4] = *(float4*)&As[kk][ty * 8 + 4];
            *(float4*)&b[0] = *(float4*)&Bs[kk][tx * 8];
            *(float4*)&b[4] = *(float4*)&Bs[kk][tx * 8 + 4];
#pragma unroll
            for (int i = 0; i < 8; i++)
#pragma unroll
                for (int j = 0; j < 8; j++)
                    acc[i][j] = fmaf(a[i], b[j], acc[i][j]);
        }
        __syncthreads();
    }

#pragma unroll
    for (int i = 0; i < 8; i++) {
        int row = bm + ty * 8 + i;
#pragma unroll
        for (int j0 = 0; j0 < 8; j0 += 4) {
            int col = bn + tx * 8 + j0;
            float4 o;
            o.x = acc[i][j0 + 0] + bias[col + 0];
            o.y = acc[i][j0 + 1] + bias[col + 1];
            o.z = acc[i][j0 + 2] + bias[col + 2];
            o.w = acc[i][j0 + 3] + bias[col + 3];
            *(float4*)&C[row * N + col] = o;
        }
    }
}

// ---------------------------------------------------------------------------
// RoPE + transpose + KV-cache emit.
// qkv: [B*N, 3D] row-major.  One thread per (b,h,n,pair).
// Writes: g_q, g_k ([B,H,N,HD], RoPE applied), kv_out = stack(pre-RoPE K, V)
// at d_out + B*N*D with layout [2,B,H,N,HD].
// ---------------------------------------------------------------------------
__global__ void rope_split(const float* __restrict__ qkv,
                           const float* __restrict__ fq,
                           const float* __restrict__ fk,
                           float* __restrict__ qout, float* __restrict__ kout,
                           float* __restrict__ kv_out)
{
    int idx = blockIdx.x * blockDim.x + threadIdx.x;  // ((b*H+h)*N+n)*64+p
    int p = idx & 63;
    int n = (idx >> 6) & (N_ - 1);
    int h = (idx >> 17) & (H_ - 1);
    int b = idx >> 21;

    const float* base = qkv + (b * N_ + n) * QC_;
    int e = 2 * p;
    float qr = base[h * HD_ + e],            qi = base[h * HD_ + e + 1];
    float kr = base[D_ + h * HD_ + e],       ki = base[D_ + h * HD_ + e + 1];
    float vr = base[2 * D_ + h * HD_ + e],   vi = base[2 * D_ + h * HD_ + e + 1];

    float aq = fq[n * (HD_ / 2) + p];
    float ak = fk[n * (HD_ / 2) + p];
    float cq = cosf(aq), sq = sinf(aq);
    float ck = cosf(ak), sk = sinf(ak);

    int o = ((b * H_ + h) * N_ + n) * HD_ + e;
    qout[o]     = qr * cq - qi * sq;
    qout[o + 1] = qr * sq + qi * cq;
    kout[o]     = kr * ck - ki * sk;
    kout[o + 1] = kr * sk + ki * ck;
    kv_out[o]            = kr;   // pre-RoPE K cache
    kv_out[o + 1]        = ki;
    kv_out[BHND + o]     = vr;   // V cache
    kv_out[BHND + o + 1] = vi;
}

// ---------------------------------------------------------------------------
// Flash attention, fp32, causal. One block per (b, h, 64-row Q tile).
// 256 threads = 8 warps; warp w owns Q rows w*8..w*8+7.
// Lane owns score columns {ln, ln+32} and O columns {ln, ln+32, ln+64, ln+96}.
// Output written as [B, N, D] (token-major) so the out-proj GEMM consumes it.
// ---------------------------------------------------------------------------
__global__ __launch_bounds__(256)
void flash_attn(const float* __restrict__ q, const float* __restrict__ k,
                const float* __restrict__ v, const int* __restrict__ amask,
                float* __restrict__ out)
{
    extern __shared__ float sm[];
    float* Qs = sm;                  // [64][128]
    float* Kt = Qs + 64 * 128;       // [128][65] transposed, conflict-free
    float* Vs = Kt + 128 * 65;       // [64][128]
    float* Ps = Vs + 64 * 128;       // [64][64]
    int*   Ms = (int*)(Ps + 64 * 64);// [64]

    const int tid = threadIdx.x;
    const int ln  = tid & 31;
    const int w   = tid >> 5;
    const int qt  = blockIdx.x;
    const int h   = blockIdx.y;
    const int b   = blockIdx.z;
    const int qstart = qt * 64;

    const float* qbh = q + (b * H_ + h) * N_ * HD_;
    const float* kbh = k + (b * H_ + h) * N_ * HD_;
    const float* vbh = v + (b * H_ + h) * N_ * HD_;

    // Q tile (row-major, coalesced)
    for (int i = tid; i < 64 * 128; i += 256)
        Qs[i] = qbh[qstart * HD_ + i];

    float m[8], l[8], O[8][4];
#pragma unroll
    for (int r = 0; r < 8; r++) {
        m[r] = -FLT_MAX; l[r] = 0.f;
        O[r][0] = O[r][1] = O[r][2] = O[r][3] = 0.f;
    }

    const int ntiles = qt + 1;   // causal: key tiles 0..qt
    const float scale = 0.08838834764831845f;  // 1/sqrt(128)
    const int c0 = ln, c1 = ln + 32;

    for (int j = 0; j < ntiles; j++) {
        int ks = j * 64;
        __syncthreads();  // previous compute done before overwriting tiles
        for (int i = tid; i < 64 * 128; i += 256) {
            int r = i >> 7, d = i & 127;
            float kval = kbh[(ks + r) * HD_ + d];
            Kt[d * 65 + r] = kval;              // transposed store, conflict-free
            Vs[i] = vbh[ks * HD_ + i];
        }
        if (tid < 64) Ms[tid] = amask[b * N_ + ks + tid];
        __syncthreads();

        // ---- S = Q K^T for this warp's 8 rows, 2 columns per lane ----
        float s0[8], s1[8];
#pragma unroll
        for (int r = 0; r < 8; r++) { s0[r] = 0.f; s1[r] = 0.f; }
#pragma unroll 4
        for (int kk = 0; kk < 128; kk++) {
            float ka = Kt[kk * 65 + c0];
            float kb = Kt[kk * 65 + c1];
            const float* qrow = &Qs[w * 8 * 128 + kk];
#pragma unroll
            for (int r = 0; r < 8; r++) {
                float qv = qrow[r * 128];       // warp-broadcast
                s0[r] = fmaf(qv, ka, s0[r]);
                s1[r] = fmaf(qv, kb, s1[r]);
            }
        }

        const bool m0ok = (Ms[c0] != 0);
        const bool m1ok = (Ms[c1] != 0);
        const int kc0 = ks + c0, kc1 = ks + c1;

        // ---- online softmax (rows are warp-local: pure shfl reductions) ----
#pragma unroll
        for (int r = 0; r < 8; r++) {
            int qr = qstart + w * 8 + r;
            float v0 = (m0ok && kc0 <= qr) ? s0[r] * scale : -FLT_MAX;
            float v1 = (m1ok && kc1 <= qr) ? s1[r] * scale : -FLT_MAX;
            float rm = fmaxf(v0, v1);
#pragma unroll
            for (int off = 16; off > 0; off >>= 1)
                rm = fmaxf(rm, __shfl_xor_sync(0xffffffffu, rm, off));
            float mn = fmaxf(m[r], rm);
            float al = expf(m[r] - mn);
            float p0 = expf(v0 - mn);
            float p1 = expf(v1 - mn);
            float rs = p0 + p1;
#pragma unroll
            for (int off = 16; off > 0; off >>= 1)
                rs += __shfl_xor_sync(0xffffffffu, rs, off);
            l[r] = l[r] * al + rs;
            m[r] = mn;
            O[r][0] *= al; O[r][1] *= al; O[r][2] *= al; O[r][3] *= al;
            Ps[(w * 8 + r) * 64 + c0] = p0;
            Ps[(w * 8 + r) * 64 + c1] = p1;
        }
        __syncwarp();   // Ps region is warp-private; warp-level RAW fence

        // ---- O += P V ----
#pragma unroll 2
        for (int c = 0; c < 64; c++) {
            float vv0 = Vs[c * 128 + ln];
            float vv1 = Vs[c * 128 + ln + 32];
            float vv2 = Vs[c * 128 + ln + 64];
            float vv3 = Vs[c * 128 + ln + 96];
            const float* prow = &Ps[w * 8 * 64 + c];
#pragma unroll
            for (int r = 0; r < 8; r++) {
                float pp = prow[r * 64];        // warp-broadcast
                O[r][0] = fmaf(pp, vv0, O[r][0]);
                O[r][1] = fmaf(pp, vv1, O[r][1]);
                O[r][2] = fmaf(pp, vv2, O[r][2]);
                O[r][3] = fmaf(pp, vv3, O[r][3]);
            }
        }
    }

    // write [b, qr, h*128 + d] token-major
#pragma unroll
    for (int r = 0; r < 8; r++) {
        int qr = qstart + w * 8 + r;
        float inv = 1.f / l[r];
        int ob = (b * N_ + qr) * D_ + h * HD_;
        out[ob + ln]      = O[r][0] * inv;
        out[ob + ln + 32] = O[r][1] * inv;
        out[ob + ln + 64] = O[r][2] * inv;
        out[ob + ln + 96] = O[r][3] * inv;
    }
}

// ---------------------------------------------------------------------------
// Launch: QKV GEMM -> RoPE/split -> flash attention -> out-proj GEMM.
// Outputs: d_out[0 : B*N*D)           = out
//          d_out[B*N*D : +2*B*H*N*HD) = next_prefix_kv (pre-RoPE K, then V)
// ---------------------------------------------------------------------------
extern "C" void kernel_launch(void* const* d_in, const int* in_sizes, int n_in,
                              void* d_out, int out_size)
{
    const float* x     = (const float*)d_in[0];
    const float* fq    = (const float*)d_in[1];
    const float* fk    = (const float*)d_in[2];
    const int*   amask = (const int*)d_in[3];
    // d_in[4] = casual_mask (exact tril; enforced by index compare instead)
    const float* Wqkv  = (const float*)d_in[5];
    const float* bqkv  = (const float*)d_in[6];
    const float* Wout  = (const float*)d_in[7];
    const float* bout  = (const float*)d_in[8];

    float* out   = (float*)d_out;
    float* kvout = out + (size_t)MR_ * D_;   // next_prefix_kv region

    float *qkv, *qb, *kb, *ab;
    cudaGetSymbolAddress((void**)&qkv, g_qkv);
    cudaGetSymbolAddress((void**)&qb, g_q);
    cudaGetSymbolAddress((void**)&kb, g_k);
    cudaGetSymbolAddress((void**)&ab, g_attn);

    // 1) QKV projection: [4096,2048] @ [2048,6144] + bias
    sgemm_bias<<<dim3(QC_ / 128, MR_ / 128), 256>>>(x, Wqkv, bqkv, qkv,
                                                    MR_, QC_, D_);

    // 2) RoPE + head transpose + KV cache emit
    rope_split<<<(B_ * H_ * N_ * (HD_ / 2)) / 256, 256>>>(qkv, fq, fk,
                                                          qb, kb, kvout);

    // 3) Causal flash attention (V read from the KV-cache region of d_out)
    const int smem_bytes = (64 * 128 + 128 * 65 + 64 * 128 + 64 * 64) * 4 + 64 * 4;
    cudaFuncSetAttribute(flash_attn, cudaFuncAttributeMaxDynamicSharedMemorySize,
                         smem_bytes);
    flash_attn<<<dim3(N_ / 64, H_, B_), 256, smem_bytes>>>(qb, kb,
                                                           kvout + BHND,
                                                           amask, ab);

    // 4) Output projection: [4096,2048] @ [2048,2048] + bias
    sgemm_bias<<<dim3(D_ / 128, MR_ / 128), 256>>>(ab, Wout, bout, out,
                                                   MR_, D_, D_);
}

// round 16
// speedup vs baseline: 1.0854x; 1.0854x over previous
#include <cuda_runtime.h>
#include <math.h>
#include <float.h>

// Problem constants
#define B_   2
#define N_   2048
#define D_   2048
#define H_   16
#define HD_  128
#define MR_  (B_ * N_)        // 4096 rows for token-major GEMMs
#define QC_  (3 * D_)         // 6144 qkv columns
#define BHND (B_ * H_ * N_ * HD_)  // 8388608

// Scratch (device globals: allocation-free per harness rules)
__device__ float g_qkv[MR_ * QC_];    // [B*N, 3D]
__device__ float g_q[BHND];           // RoPE'd Q  [B,H,N,HD]
__device__ float g_k[BHND];           // RoPE'd K  [B,H,N,HD]
__device__ float g_attn[MR_ * D_];    // attn output [B,N,D]

// ---------------------------------------------------------------------------
// f32x2 packed-FMA helpers (sm_103a; ptxas never auto-fuses these)
// ---------------------------------------------------------------------------
typedef unsigned long long ull;

union U4 { float4 f4; float f[4]; ull u[2]; };

__device__ __forceinline__ ull splat2(float x) {
    ull r;
    asm("mov.b64 %0, {%1, %1};" : "=l"(r) : "f"(x));
    return r;
}
__device__ __forceinline__ ull ffma2(ull a, ull b, ull c) {
    ull d;
    asm("fma.rn.f32x2 %0, %1, %2, %3;" : "=l"(d) : "l"(a), "l"(b), "l"(c));
    return d;
}
__device__ __forceinline__ ull fmul2(ull a, ull b) {
    ull d;
    asm("mul.rn.f32x2 %0, %1, %2;" : "=l"(d) : "l"(a), "l"(b));
    return d;
}
__device__ __forceinline__ float2 unpack2(ull v) {
    float2 f;
    asm("mov.b64 {%0, %1}, %2;" : "=f"(f.x), "=f"(f.y) : "l"(v));
    return f;
}

// ---------------------------------------------------------------------------
// SGEMM: C[M,N] = A[M,K] @ B[K,N] + bias[N].  128x128 blocktile, BK=16,
// 256 threads, 8x8 microtile per thread, f32x2 packed FMA (pairs over n).
// ---------------------------------------------------------------------------
__global__ __launch_bounds__(256)
void sgemm_bias(const float* __restrict__ A, const float* __restrict__ Bm,
                const float* __restrict__ bias, float* __restrict__ C,
                int M, int N, int K)
{
    __shared__ float As[16][128];   // transposed A tile: As[k][m]
    __shared__ float Bs[16][128];   // Bs[k][n]

    const int tid = threadIdx.x;
    const int bm = blockIdx.y * 128;
    const int bn = blockIdx.x * 128;
    const int tx = tid & 15;        // 16 col-groups
    const int ty = tid >> 4;        // 16 row-groups

    ull acc[8][4];                  // acc[i][j2] = (C[i][2j2], C[i][2j2+1])
#pragma unroll
    for (int i = 0; i < 8; i++)
#pragma unroll
        for (int j = 0; j < 4; j++) acc[i][j] = 0ULL;

    const float* Ab = A + bm * K;

    for (int k0 = 0; k0 < K; k0 += 16) {
        // load A tile (128x16) transposed into As
#pragma unroll
        for (int i = 0; i < 2; i++) {
            int f = tid + i * 256;           // 0..511 float4 slots
            int r = f >> 2;                  // row 0..127
            int kc = (f & 3) << 2;           // k offset 0,4,8,12
            float4 v = *(const float4*)&Ab[r * K + k0 + kc];
            As[kc + 0][r] = v.x;
            As[kc + 1][r] = v.y;
            As[kc + 2][r] = v.z;
            As[kc + 3][r] = v.w;
        }
        // load B tile (16x128)
#pragma unroll
        for (int i = 0; i < 2; i++) {
            int f = tid + i * 256;
            int r = f >> 5;                  // k row 0..15
            int c = (f & 31) << 2;           // col 0..124
            *(float4*)&Bs[r][c] = *(const float4*)&Bm[(k0 + r) * N + bn + c];
        }
        __syncthreads();

#pragma unroll
        for (int kk = 0; kk < 16; kk++) {
            float a[8];
            *(float4*)&a[0] = *(float4*)&As[kk][ty * 8];
            *(float4*)&a[4] = *(float4*)&As[kk][ty * 8 + 4];
            U4 b0, b1;
            b0.f4 = *(float4*)&Bs[kk][tx * 8];
            b1.f4 = *(float4*)&Bs[kk][tx * 8 + 4];
            ull bp0 = b0.u[0], bp1 = b0.u[1], bp2 = b1.u[0], bp3 = b1.u[1];
#pragma unroll
            for (int i = 0; i < 8; i++) {
                ull a2 = splat2(a[i]);
                acc[i][0] = ffma2(a2, bp0, acc[i][0]);
                acc[i][1] = ffma2(a2, bp1, acc[i][1]);
                acc[i][2] = ffma2(a2, bp2, acc[i][2]);
                acc[i][3] = ffma2(a2, bp3, acc[i][3]);
            }
        }
        __syncthreads();
    }

    float4 bb0 = *(const float4*)&bias[bn + tx * 8];
    float4 bb1 = *(const float4*)&bias[bn + tx * 8 + 4];
#pragma unroll
    for (int i = 0; i < 8; i++) {
        int row = bm + ty * 8 + i;
        float2 p0 = unpack2(acc[i][0]);
        float2 p1 = unpack2(acc[i][1]);
        float2 p2 = unpack2(acc[i][2]);
        float2 p3 = unpack2(acc[i][3]);
        float4 o0, o1;
        o0.x = p0.x + bb0.x; o0.y = p0.y + bb0.y;
        o0.z = p1.x + bb0.z; o0.w = p1.y + bb0.w;
        o1.x = p2.x + bb1.x; o1.y = p2.y + bb1.y;
        o1.z = p3.x + bb1.z; o1.w = p3.y + bb1.w;
        *(float4*)&C[row * N + bn + tx * 8] = o0;
        *(float4*)&C[row * N + bn + tx * 8 + 4] = o1;
    }
}

// ---------------------------------------------------------------------------
// RoPE + transpose + KV-cache emit (unchanged).
// ---------------------------------------------------------------------------
__global__ void rope_split(const float* __restrict__ qkv,
                           const float* __restrict__ fq,
                           const float* __restrict__ fk,
                           float* __restrict__ qout, float* __restrict__ kout,
                           float* __restrict__ kv_out)
{
    int idx = blockIdx.x * blockDim.x + threadIdx.x;  // ((b*H+h)*N+n)*64+p
    int p = idx & 63;
    int n = (idx >> 6) & (N_ - 1);
    int h = (idx >> 17) & (H_ - 1);
    int b = idx >> 21;

    const float* base = qkv + (b * N_ + n) * QC_;
    int e = 2 * p;
    float qr = base[h * HD_ + e],            qi = base[h * HD_ + e + 1];
    float kr = base[D_ + h * HD_ + e],       ki = base[D_ + h * HD_ + e + 1];
    float vr = base[2 * D_ + h * HD_ + e],   vi = base[2 * D_ + h * HD_ + e + 1];

    float aq = fq[n * (HD_ / 2) + p];
    float ak = fk[n * (HD_ / 2) + p];
    float cq = cosf(aq), sq = sinf(aq);
    float ck = cosf(ak), sk = sinf(ak);

    int o = ((b * H_ + h) * N_ + n) * HD_ + e;
    qout[o]     = qr * cq - qi * sq;
    qout[o + 1] = qr * sq + qi * cq;
    kout[o]     = kr * ck - ki * sk;
    kout[o + 1] = kr * sk + ki * ck;
    kv_out[o]            = kr;   // pre-RoPE K cache
    kv_out[o + 1]        = ki;
    kv_out[BHND + o]     = vr;   // V cache
    kv_out[BHND + o + 1] = vi;
}

// ---------------------------------------------------------------------------
// Flash attention, fp32, causal. One block per (b, h, 64-row Q tile).
// 256 threads = 8 warps; warp w owns Q rows w*8..w*8+7.
// QK: lane owns score cols {ln, ln+32}; K tile row-major with per-row XOR
//     float4 swizzle (conflict-free row reads); accumulator pairs over kk
//     (both FMA2 operands come free from float4 loads — zero packing MOVs).
// PV: lane owns O cols {4ln..4ln+3}; V float4 reads + P float4 broadcasts.
// ---------------------------------------------------------------------------
__global__ __launch_bounds__(256)
void flash_attn(const float* __restrict__ q, const float* __restrict__ k,
                const float* __restrict__ v, const int* __restrict__ amask,
                float* __restrict__ out)
{
    extern __shared__ float sm[];
    float* Qs = sm;                  // [64][128] linear
    float* Ks = Qs + 64 * 128;       // [64][32 float4], XOR-swizzled
    float* Vs = Ks + 64 * 128;       // [64][128] linear
    float* Ps = Vs + 64 * 128;       // [64][64]
    int*   Ms = (int*)(Ps + 64 * 64);// [64]

    const int tid = threadIdx.x;
    const int ln  = tid & 31;
    const int w   = tid >> 5;
    const int qt  = blockIdx.x;
    const int h   = blockIdx.y;
    const int b   = blockIdx.z;
    const int qstart = qt * 64;

    const float* qbh = q + (b * H_ + h) * N_ * HD_;
    const float* kbh = k + (b * H_ + h) * N_ * HD_;
    const float* vbh = v + (b * H_ + h) * N_ * HD_;

    // Q tile (row-major, coalesced float4)
    for (int i4 = tid; i4 < 2048; i4 += 256)
        *(float4*)&Qs[i4 * 4] = *(const float4*)&qbh[qstart * HD_ + i4 * 4];

    float m[8], l[8];
    ull O2[8][2];                    // pairs: cols (4ln,4ln+1),(4ln+2,4ln+3)
#pragma unroll
    for (int r = 0; r < 8; r++) {
        m[r] = -FLT_MAX; l[r] = 0.f;
        O2[r][0] = 0ULL; O2[r][1] = 0ULL;
    }

    const int ntiles = qt + 1;   // causal: key tiles 0..qt
    const float scale = 0.08838834764831845f;  // 1/sqrt(128)
    const int c0 = ln, c1 = ln + 32;
    const float* qbase = &Qs[w * 8 * 128];
    float* prow_base = &Ps[w * 8 * 64];

    for (int j = 0; j < ntiles; j++) {
        int ks = j * 64;
        __syncthreads();  // previous compute done before overwriting tiles
        for (int i4 = tid; i4 < 2048; i4 += 256) {
            int r = i4 >> 5, ch = i4 & 31;      // row, float4 chunk
            float4 kv = *(const float4*)&kbh[(ks + r) * HD_ + ch * 4];
            *(float4*)&Ks[(r * 32 + (ch ^ (r & 31))) * 4] = kv;  // swizzled
            float4 vv = *(const float4*)&vbh[(ks + r) * HD_ + ch * 4];
            *(float4*)&Vs[r * 128 + ch * 4] = vv;
        }
        if (tid < 64) Ms[tid] = amask[b * N_ + ks + tid];
        __syncthreads();

        // ---- S = Q K^T : accumulator pairs over kk, no packing MOVs ----
        ull sA[8], sB[8];
#pragma unroll
        for (int r = 0; r < 8; r++) { sA[r] = 0ULL; sB[r] = 0ULL; }
#pragma unroll 8
        for (int kk = 0; kk < 128; kk += 4) {
            int ch = kk >> 2;
            U4 k0, k1;
            k0.f4 = *(float4*)&Ks[(c0 * 32 + (ch ^ ln)) * 4];
            k1.f4 = *(float4*)&Ks[(c1 * 32 + (ch ^ ln)) * 4];
#pragma unroll
            for (int r = 0; r < 8; r++) {
                U4 qv;
                qv.f4 = *(const float4*)&qbase[r * 128 + kk];  // warp-broadcast
                sA[r] = ffma2(qv.u[0], k0.u[0], sA[r]);
                sA[r] = ffma2(qv.u[1], k0.u[1], sA[r]);
                sB[r] = ffma2(qv.u[0], k1.u[0], sB[r]);
                sB[r] = ffma2(qv.u[1], k1.u[1], sB[r]);
            }
        }

        const bool m0ok = (Ms[c0] != 0);
        const bool m1ok = (Ms[c1] != 0);
        const int kc0 = ks + c0, kc1 = ks + c1;

        // ---- online softmax (rows warp-local: pure shfl reductions) ----
#pragma unroll
        for (int r = 0; r < 8; r++) {
            float2 fa = unpack2(sA[r]);
            float2 fb = unpack2(sB[r]);
            float sc0 = fa.x + fa.y;
            float sc1 = fb.x + fb.y;
            int qr = qstart + w * 8 + r;
            float v0 = (m0ok && kc0 <= qr) ? sc0 * scale : -FLT_MAX;
            float v1 = (m1ok && kc1 <= qr) ? sc1 * scale : -FLT_MAX;
            float rm = fmaxf(v0, v1);
#pragma unroll
            for (int off = 16; off > 0; off >>= 1)
                rm = fmaxf(rm, __shfl_xor_sync(0xffffffffu, rm, off));
            float mn = fmaxf(m[r], rm);
            float al = expf(m[r] - mn);
            float p0 = expf(v0 - mn);
            float p1 = expf(v1 - mn);
            float rs = p0 + p1;
#pragma unroll
            for (int off = 16; off > 0; off >>= 1)
                rs += __shfl_xor_sync(0xffffffffu, rs, off);
            l[r] = l[r] * al + rs;
            m[r] = mn;
            ull al2 = splat2(al);
            O2[r][0] = fmul2(O2[r][0], al2);
            O2[r][1] = fmul2(O2[r][1], al2);
            prow_base[r * 64 + c0] = p0;
            prow_base[r * 64 + c1] = p1;
        }
        __syncwarp();   // Ps region is warp-private; warp-level RAW fence

        // ---- O += P V : V float4 per lane, P float4 broadcast ----
#pragma unroll 4
        for (int c = 0; c < 64; c += 4) {
            U4 v0, v1, v2, v3;
            v0.f4 = *(float4*)&Vs[(c + 0) * 128 + 4 * ln];
            v1.f4 = *(float4*)&Vs[(c + 1) * 128 + 4 * ln];
            v2.f4 = *(float4*)&Vs[(c + 2) * 128 + 4 * ln];
            v3.f4 = *(float4*)&Vs[(c + 3) * 128 + 4 * ln];
#pragma unroll
            for (int r = 0; r < 8; r++) {
                U4 p;
                p.f4 = *(const float4*)&prow_base[r * 64 + c];  // broadcast
                ull px = splat2(p.f[0]);
                O2[r][0] = ffma2(px, v0.u[0], O2[r][0]);
                O2[r][1] = ffma2(px, v0.u[1], O2[r][1]);
                ull py = splat2(p.f[1]);
                O2[r][0] = ffma2(py, v1.u[0], O2[r][0]);
                O2[r][1] = ffma2(py, v1.u[1], O2[r][1]);
                ull pz = splat2(p.f[2]);
                O2[r][0] = ffma2(pz, v2.u[0], O2[r][0]);
                O2[r][1] = ffma2(pz, v2.u[1], O2[r][1]);
                ull pw = splat2(p.f[3]);
                O2[r][0] = ffma2(pw, v3.u[0], O2[r][0]);
                O2[r][1] = ffma2(pw, v3.u[1], O2[r][1]);
            }
        }
    }

    // write [b, qr, h*128 + d] token-major; lane owns cols 4ln..4ln+3
#pragma unroll
    for (int r = 0; r < 8; r++) {
        int qr = qstart + w * 8 + r;
        float inv = 1.f / l[r];
        float2 a = unpack2(O2[r][0]);
        float2 c = unpack2(O2[r][1]);
        float4 o;
        o.x = a.x * inv; o.y = a.y * inv;
        o.z = c.x * inv; o.w = c.y * inv;
        int ob = (b * N_ + qr) * D_ + h * HD_ + 4 * ln;
        *(float4*)&out[ob] = o;
    }
}

// ---------------------------------------------------------------------------
// Launch: QKV GEMM -> RoPE/split -> flash attention -> out-proj GEMM.
// Outputs: d_out[0 : B*N*D)           = out
//          d_out[B*N*D : +2*B*H*N*HD) = next_prefix_kv (pre-RoPE K, then V)
// ---------------------------------------------------------------------------
extern "C" void kernel_launch(void* const* d_in, const int* in_sizes, int n_in,
                              void* d_out, int out_size)
{
    const float* x     = (const float*)d_in[0];
    const float* fq    = (const float*)d_in[1];
    const float* fk    = (const float*)d_in[2];
    const int*   amask = (const int*)d_in[3];
    // d_in[4] = casual_mask (exact tril; enforced by index compare instead)
    const float* Wqkv  = (const float*)d_in[5];
    const float* bqkv  = (const float*)d_in[6];
    const float* Wout  = (const float*)d_in[7];
    const float* bout  = (const float*)d_in[8];

    float* out   = (float*)d_out;
    float* kvout = out + (size_t)MR_ * D_;   // next_prefix_kv region

    float *qkv, *qb, *kb, *ab;
    cudaGetSymbolAddress((void**)&qkv, g_qkv);
    cudaGetSymbolAddress((void**)&qb, g_q);
    cudaGetSymbolAddress((void**)&kb, g_k);
    cudaGetSymbolAddress((void**)&ab, g_attn);

    // 1) QKV projection: [4096,2048] @ [2048,6144] + bias
    sgemm_bias<<<dim3(QC_ / 128, MR_ / 128), 256>>>(x, Wqkv, bqkv, qkv,
                                                    MR_, QC_, D_);

    // 2) RoPE + head transpose + KV cache emit
    rope_split<<<(B_ * H_ * N_ * (HD_ / 2)) / 256, 256>>>(qkv, fq, fk,
                                                          qb, kb, kvout);

    // 3) Causal flash attention (V read from the KV-cache region of d_out)
    const int smem_bytes = (3 * 64 * 128 + 64 * 64) * 4 + 64 * 4;
    cudaFuncSetAttribute(flash_attn, cudaFuncAttributeMaxDynamicSharedMemorySize,
                         smem_bytes);
    flash_attn<<<dim3(N_ / 64, H_, B_), 256, smem_bytes>>>(qb, kb,
                                                           kvout + BHND,
                                                           amask, ab);

    // 4) Output projection: [4096,2048] @ [2048,2048] + bias
    sgemm_bias<<<dim3(D_ / 128, MR_ / 128), 256>>>(ab, Wout, bout, out,
                                                   MR_, D_, D_);
}

// round 17
// speedup vs baseline: 1.1750x; 1.0825x over previous
#include <cuda_runtime.h>
#include <math.h>
#include <float.h>

// Problem constants
#define B_   2
#define N_   2048
#define D_   2048
#define H_   16
#define HD_  128
#define MR_  (B_ * N_)        // 4096 rows for token-major GEMMs
#define QC_  (3 * D_)         // 6144 qkv columns
#define BHND (B_ * H_ * N_ * HD_)  // 8388608

// Scratch (device globals: allocation-free per harness rules)
__device__ float g_qkv[MR_ * QC_];    // [B*N, 3D]
__device__ float g_q[BHND];           // RoPE'd Q  [B,H,N,HD]
__device__ float g_k[BHND];           // RoPE'd K  [B,H,N,HD]
__device__ float g_attn[MR_ * D_];    // attn output [B,N,D]

// ---------------------------------------------------------------------------
// f32x2 packed-FMA helpers (sm_103a; ptxas never auto-fuses these)
// ---------------------------------------------------------------------------
typedef unsigned long long ull;

union U4 { float4 f4; float f[4]; ull u[2]; };

__device__ __forceinline__ ull splat2(float x) {
    ull r;
    asm("mov.b64 %0, {%1, %1};" : "=l"(r) : "f"(x));
    return r;
}
__device__ __forceinline__ ull ffma2(ull a, ull b, ull c) {
    ull d;
    asm("fma.rn.f32x2 %0, %1, %2, %3;" : "=l"(d) : "l"(a), "l"(b), "l"(c));
    return d;
}
__device__ __forceinline__ ull fmul2(ull a, ull b) {
    ull d;
    asm("mul.rn.f32x2 %0, %1, %2;" : "=l"(d) : "l"(a), "l"(b));
    return d;
}
__device__ __forceinline__ float2 unpack2(ull v) {
    float2 f;
    asm("mov.b64 {%0, %1}, %2;" : "=f"(f.x), "=f"(f.y) : "l"(v));
    return f;
}

// ---------------------------------------------------------------------------
// SGEMM: C[M,N] = A[M,K] @ B[K,N] + bias[N].  128x128 blocktile, BK=16,
// 256 threads, 8x8 microtile, f32x2 packed FMA, double-buffered smem with
// register-staged GMEM prefetch (one __syncthreads per k-tile).
// ---------------------------------------------------------------------------
#define APAD 132   // padded lead dim for transposed A tile (2-way max conflict)

__global__ __launch_bounds__(256, 2)
void sgemm_bias(const float* __restrict__ A, const float* __restrict__ Bm,
                const float* __restrict__ bias, float* __restrict__ C,
                int M, int N, int K)
{
    __shared__ float As[2][16][APAD];   // transposed A tile: As[buf][k][m]
    __shared__ float Bs[2][16][128];    // Bs[buf][k][n]

    const int tid = threadIdx.x;
    const int bm = blockIdx.y * 128;
    const int bn = blockIdx.x * 128;
    const int tx = tid & 15;        // 16 col-groups
    const int ty = tid >> 4;        // 16 row-groups

    // GMEM load coordinates (fixed per thread)
    const int arow0 = tid >> 2;               // A rows for i=0 / i=1
    const int arow1 = (tid + 256) >> 2;
    const int akc0  = (tid & 3) << 2;         // k offsets
    const int brow0 = tid >> 5;               // B k-rows
    const int brow1 = (tid + 256) >> 5;
    const int bc    = (tid & 31) << 2;        // B col

    const float* Ab = A + bm * K;
    const float* Bb = Bm + bn;

    ull acc[8][4];
#pragma unroll
    for (int i = 0; i < 8; i++)
#pragma unroll
        for (int j = 0; j < 4; j++) acc[i][j] = 0ULL;

    float4 aR0, aR1, bR0, bR1;

    // ---- prologue: load tile 0 ----
    aR0 = *(const float4*)&Ab[arow0 * K + akc0];
    aR1 = *(const float4*)&Ab[arow1 * K + akc0];
    bR0 = *(const float4*)&Bb[brow0 * N + bc];
    bR1 = *(const float4*)&Bb[brow1 * N + bc];
    As[0][akc0 + 0][arow0] = aR0.x;
    As[0][akc0 + 1][arow0] = aR0.y;
    As[0][akc0 + 2][arow0] = aR0.z;
    As[0][akc0 + 3][arow0] = aR0.w;
    As[0][akc0 + 0][arow1] = aR1.x;
    As[0][akc0 + 1][arow1] = aR1.y;
    As[0][akc0 + 2][arow1] = aR1.z;
    As[0][akc0 + 3][arow1] = aR1.w;
    *(float4*)&Bs[0][brow0][bc] = bR0;
    *(float4*)&Bs[0][brow1][bc] = bR1;
    __syncthreads();

    const int T = K >> 4;
    int buf = 0;
    for (int t = 0; t < T; t++) {
        // prefetch next tile GMEM -> regs (latency hides under compute)
        if (t + 1 < T) {
            int k0 = (t + 1) << 4;
            aR0 = *(const float4*)&Ab[arow0 * K + k0 + akc0];
            aR1 = *(const float4*)&Ab[arow1 * K + k0 + akc0];
            bR0 = *(const float4*)&Bb[(k0 + brow0) * N + bc];
            bR1 = *(const float4*)&Bb[(k0 + brow1) * N + bc];
        }

        // compute on current buffer
#pragma unroll
        for (int kk = 0; kk < 16; kk++) {
            float a[8];
            *(float4*)&a[0] = *(float4*)&As[buf][kk][ty * 8];
            *(float4*)&a[4] = *(float4*)&As[buf][kk][ty * 8 + 4];
            U4 b0, b1;
            b0.f4 = *(float4*)&Bs[buf][kk][tx * 8];
            b1.f4 = *(float4*)&Bs[buf][kk][tx * 8 + 4];
            ull bp0 = b0.u[0], bp1 = b0.u[1], bp2 = b1.u[0], bp3 = b1.u[1];
#pragma unroll
            for (int i = 0; i < 8; i++) {
                ull a2 = splat2(a[i]);
                acc[i][0] = ffma2(a2, bp0, acc[i][0]);
                acc[i][1] = ffma2(a2, bp1, acc[i][1]);
                acc[i][2] = ffma2(a2, bp2, acc[i][2]);
                acc[i][3] = ffma2(a2, bp3, acc[i][3]);
            }
        }

        // stage next tile regs -> alternate smem buffer
        if (t + 1 < T) {
            int nb = buf ^ 1;
            As[nb][akc0 + 0][arow0] = aR0.x;
            As[nb][akc0 + 1][arow0] = aR0.y;
            As[nb][akc0 + 2][arow0] = aR0.z;
            As[nb][akc0 + 3][arow0] = aR0.w;
            As[nb][akc0 + 0][arow1] = aR1.x;
            As[nb][akc0 + 1][arow1] = aR1.y;
            As[nb][akc0 + 2][arow1] = aR1.z;
            As[nb][akc0 + 3][arow1] = aR1.w;
            *(float4*)&Bs[nb][brow0][bc] = bR0;
            *(float4*)&Bs[nb][brow1][bc] = bR1;
        }
        __syncthreads();
        buf ^= 1;
    }

    float4 bb0 = *(const float4*)&bias[bn + tx * 8];
    float4 bb1 = *(const float4*)&bias[bn + tx * 8 + 4];
#pragma unroll
    for (int i = 0; i < 8; i++) {
        int row = bm + ty * 8 + i;
        float2 p0 = unpack2(acc[i][0]);
        float2 p1 = unpack2(acc[i][1]);
        float2 p2 = unpack2(acc[i][2]);
        float2 p3 = unpack2(acc[i][3]);
        float4 o0, o1;
        o0.x = p0.x + bb0.x; o0.y = p0.y + bb0.y;
        o0.z = p1.x + bb0.z; o0.w = p1.y + bb0.w;
        o1.x = p2.x + bb1.x; o1.y = p2.y + bb1.y;
        o1.z = p3.x + bb1.z; o1.w = p3.y + bb1.w;
        *(float4*)&C[row * N + bn + tx * 8] = o0;
        *(float4*)&C[row * N + bn + tx * 8 + 4] = o1;
    }
}

// ---------------------------------------------------------------------------
// RoPE + transpose + KV-cache emit (unchanged).
// ---------------------------------------------------------------------------
__global__ void rope_split(const float* __restrict__ qkv,
                           const float* __restrict__ fq,
                           const float* __restrict__ fk,
                           float* __restrict__ qout, float* __restrict__ kout,
                           float* __restrict__ kv_out)
{
    int idx = blockIdx.x * blockDim.x + threadIdx.x;  // ((b*H+h)*N+n)*64+p
    int p = idx & 63;
    int n = (idx >> 6) & (N_ - 1);
    int h = (idx >> 17) & (H_ - 1);
    int b = idx >> 21;

    const float* base = qkv + (b * N_ + n) * QC_;
    int e = 2 * p;
    float qr = base[h * HD_ + e],            qi = base[h * HD_ + e + 1];
    float kr = base[D_ + h * HD_ + e],       ki = base[D_ + h * HD_ + e + 1];
    float vr = base[2 * D_ + h * HD_ + e],   vi = base[2 * D_ + h * HD_ + e + 1];

    float aq = fq[n * (HD_ / 2) + p];
    float ak = fk[n * (HD_ / 2) + p];
    float cq = cosf(aq), sq = sinf(aq);
    float ck = cosf(ak), sk = sinf(ak);

    int o = ((b * H_ + h) * N_ + n) * HD_ + e;
    qout[o]     = qr * cq - qi * sq;
    qout[o + 1] = qr * sq + qi * cq;
    kout[o]     = kr * ck - ki * sk;
    kout[o + 1] = kr * sk + ki * ck;
    kv_out[o]            = kr;   // pre-RoPE K cache
    kv_out[o + 1]        = ki;
    kv_out[BHND + o]     = vr;   // V cache
    kv_out[BHND + o + 1] = vi;
}

// ---------------------------------------------------------------------------
// Flash attention, fp32, causal (unchanged from R15). One block per
// (b, h, 64-row Q tile); 256 threads; f32x2 throughout.
// ---------------------------------------------------------------------------
__global__ __launch_bounds__(256)
void flash_attn(const float* __restrict__ q, const float* __restrict__ k,
                const float* __restrict__ v, const int* __restrict__ amask,
                float* __restrict__ out)
{
    extern __shared__ float sm[];
    float* Qs = sm;                  // [64][128] linear
    float* Ks = Qs + 64 * 128;       // [64][32 float4], XOR-swizzled
    float* Vs = Ks + 64 * 128;       // [64][128] linear
    float* Ps = Vs + 64 * 128;       // [64][64]
    int*   Ms = (int*)(Ps + 64 * 64);// [64]

    const int tid = threadIdx.x;
    const int ln  = tid & 31;
    const int w   = tid >> 5;
    const int qt  = blockIdx.x;
    const int h   = blockIdx.y;
    const int b   = blockIdx.z;
    const int qstart = qt * 64;

    const float* qbh = q + (b * H_ + h) * N_ * HD_;
    const float* kbh = k + (b * H_ + h) * N_ * HD_;
    const float* vbh = v + (b * H_ + h) * N_ * HD_;

    for (int i4 = tid; i4 < 2048; i4 += 256)
        *(float4*)&Qs[i4 * 4] = *(const float4*)&qbh[qstart * HD_ + i4 * 4];

    float m[8], l[8];
    ull O2[8][2];
#pragma unroll
    for (int r = 0; r < 8; r++) {
        m[r] = -FLT_MAX; l[r] = 0.f;
        O2[r][0] = 0ULL; O2[r][1] = 0ULL;
    }

    const int ntiles = qt + 1;
    const float scale = 0.08838834764831845f;  // 1/sqrt(128)
    const int c0 = ln, c1 = ln + 32;
    const float* qbase = &Qs[w * 8 * 128];
    float* prow_base = &Ps[w * 8 * 64];

    for (int j = 0; j < ntiles; j++) {
        int ks = j * 64;
        __syncthreads();
        for (int i4 = tid; i4 < 2048; i4 += 256) {
            int r = i4 >> 5, ch = i4 & 31;
            float4 kv = *(const float4*)&kbh[(ks + r) * HD_ + ch * 4];
            *(float4*)&Ks[(r * 32 + (ch ^ (r & 31))) * 4] = kv;
            float4 vv = *(const float4*)&vbh[(ks + r) * HD_ + ch * 4];
            *(float4*)&Vs[r * 128 + ch * 4] = vv;
        }
        if (tid < 64) Ms[tid] = amask[b * N_ + ks + tid];
        __syncthreads();

        ull sA[8], sB[8];
#pragma unroll
        for (int r = 0; r < 8; r++) { sA[r] = 0ULL; sB[r] = 0ULL; }
#pragma unroll 8
        for (int kk = 0; kk < 128; kk += 4) {
            int ch = kk >> 2;
            U4 k0, k1;
            k0.f4 = *(float4*)&Ks[(c0 * 32 + (ch ^ ln)) * 4];
            k1.f4 = *(float4*)&Ks[(c1 * 32 + (ch ^ ln)) * 4];
#pragma unroll
            for (int r = 0; r < 8; r++) {
                U4 qv;
                qv.f4 = *(const float4*)&qbase[r * 128 + kk];
                sA[r] = ffma2(qv.u[0], k0.u[0], sA[r]);
                sA[r] = ffma2(qv.u[1], k0.u[1], sA[r]);
                sB[r] = ffma2(qv.u[0], k1.u[0], sB[r]);
                sB[r] = ffma2(qv.u[1], k1.u[1], sB[r]);
            }
        }

        const bool m0ok = (Ms[c0] != 0);
        const bool m1ok = (Ms[c1] != 0);
        const int kc0 = ks + c0, kc1 = ks + c1;

#pragma unroll
        for (int r = 0; r < 8; r++) {
            float2 fa = unpack2(sA[r]);
            float2 fb = unpack2(sB[r]);
            float sc0 = fa.x + fa.y;
            float sc1 = fb.x + fb.y;
            int qr = qstart + w * 8 + r;
            float v0 = (m0ok && kc0 <= qr) ? sc0 * scale : -FLT_MAX;
            float v1 = (m1ok && kc1 <= qr) ? sc1 * scale : -FLT_MAX;
            float rm = fmaxf(v0, v1);
#pragma unroll
            for (int off = 16; off > 0; off >>= 1)
                rm = fmaxf(rm, __shfl_xor_sync(0xffffffffu, rm, off));
            float mn = fmaxf(m[r], rm);
            float al = expf(m[r] - mn);
            float p0 = expf(v0 - mn);
            float p1 = expf(v1 - mn);
            float rs = p0 + p1;
#pragma unroll
            for (int off = 16; off > 0; off >>= 1)
                rs += __shfl_xor_sync(0xffffffffu, rs, off);
            l[r] = l[r] * al + rs;
            m[r] = mn;
            ull al2 = splat2(al);
            O2[r][0] = fmul2(O2[r][0], al2);
            O2[r][1] = fmul2(O2[r][1], al2);
            prow_base[r * 64 + c0] = p0;
            prow_base[r * 64 + c1] = p1;
        }
        __syncwarp();

#pragma unroll 4
        for (int c = 0; c < 64; c += 4) {
            U4 v0, v1, v2, v3;
            v0.f4 = *(float4*)&Vs[(c + 0) * 128 + 4 * ln];
            v1.f4 = *(float4*)&Vs[(c + 1) * 128 + 4 * ln];
            v2.f4 = *(float4*)&Vs[(c + 2) * 128 + 4 * ln];
            v3.f4 = *(float4*)&Vs[(c + 3) * 128 + 4 * ln];
#pragma unroll
            for (int r = 0; r < 8; r++) {
                U4 p;
                p.f4 = *(const float4*)&prow_base[r * 64 + c];
                ull px = splat2(p.f[0]);
                O2[r][0] = ffma2(px, v0.u[0], O2[r][0]);
                O2[r][1] = ffma2(px, v0.u[1], O2[r][1]);
                ull py = splat2(p.f[1]);
                O2[r][0] = ffma2(py, v1.u[0], O2[r][0]);
                O2[r][1] = ffma2(py, v1.u[1], O2[r][1]);
                ull pz = splat2(p.f[2]);
                O2[r][0] = ffma2(pz, v2.u[0], O2[r][0]);
                O2[r][1] = ffma2(pz, v2.u[1], O2[r][1]);
                ull pw = splat2(p.f[3]);
                O2[r][0] = ffma2(pw, v3.u[0], O2[r][0]);
                O2[r][1] = ffma2(pw, v3.u[1], O2[r][1]);
            }
        }
    }

#pragma unroll
    for (int r = 0; r < 8; r++) {
        int qr = qstart + w * 8 + r;
        float inv = 1.f / l[r];
        float2 a = unpack2(O2[r][0]);
        float2 c = unpack2(O2[r][1]);
        float4 o;
        o.x = a.x * inv; o.y = a.y * inv;
        o.z = c.x * inv; o.w = c.y * inv;
        int ob = (b * N_ + qr) * D_ + h * HD_ + 4 * ln;
        *(float4*)&out[ob] = o;
    }
}

// ---------------------------------------------------------------------------
// Launch: QKV GEMM -> RoPE/split -> flash attention -> out-proj GEMM.
// Outputs: d_out[0 : B*N*D)           = out
//          d_out[B*N*D : +2*B*H*N*HD) = next_prefix_kv (pre-RoPE K, then V)
// ---------------------------------------------------------------------------
extern "C" void kernel_launch(void* const* d_in, const int* in_sizes, int n_in,
                              void* d_out, int out_size)
{
    const float* x     = (const float*)d_in[0];
    const float* fq    = (const float*)d_in[1];
    const float* fk    = (const float*)d_in[2];
    const int*   amask = (const int*)d_in[3];
    // d_in[4] = casual_mask (exact tril; enforced by index compare instead)
    const float* Wqkv  = (const float*)d_in[5];
    const float* bqkv  = (const float*)d_in[6];
    const float* Wout  = (const float*)d_in[7];
    const float* bout  = (const float*)d_in[8];

    float* out   = (float*)d_out;
    float* kvout = out + (size_t)MR_ * D_;   // next_prefix_kv region

    float *qkv, *qb, *kb, *ab;
    cudaGetSymbolAddress((void**)&qkv, g_qkv);
    cudaGetSymbolAddress((void**)&qb, g_q);
    cudaGetSymbolAddress((void**)&kb, g_k);
    cudaGetSymbolAddress((void**)&ab, g_attn);

    // 1) QKV projection: [4096,2048] @ [2048,6144] + bias
    sgemm_bias<<<dim3(QC_ / 128, MR_ / 128), 256>>>(x, Wqkv, bqkv, qkv,
                                                    MR_, QC_, D_);

    // 2) RoPE + head transpose + KV cache emit
    rope_split<<<(B_ * H_ * N_ * (HD_ / 2)) / 256, 256>>>(qkv, fq, fk,
                                                          qb, kb, kvout);

    // 3) Causal flash attention (V read from the KV-cache region of d_out)
    const int smem_bytes = (3 * 64 * 128 + 64 * 64) * 4 + 64 * 4;
    cudaFuncSetAttribute(flash_attn, cudaFuncAttributeMaxDynamicSharedMemorySize,
                         smem_bytes);
    flash_attn<<<dim3(N_ / 64, H_, B_), 256, smem_bytes>>>(qb, kb,
                                                           kvout + BHND,
                                                           amask, ab);

    // 4) Output projection: [4096,2048] @ [2048,2048] + bias
    sgemm_bias<<<dim3(D_ / 128, MR_ / 128), 256>>>(ab, Wout, bout, out,
                                                   MR_, D_, D_);
}